// round 3
// baseline (speedup 1.0000x reference)
#include <cuda_runtime.h>
#include <math.h>

#define NPOS   (512*1024)     // H*W spatial positions
#define BATCH  8
#define KBINS  16
#define CBINS  4
#define BLOCK  128
#define GRID   592            // 148 SMs x 4 CTAs -> one balanced wave

// Global fp64 accumulators (zeroed by zero_acc each launch -> graph-replay safe)
__device__ double g_pcl[KBINS*CBINS];
__device__ double g_pc[KBINS];
__device__ double g_pl[CBINS];

__global__ void zero_acc() {
    int i = threadIdx.x;
    if (i < KBINS*CBINS) g_pcl[i] = 0.0;
    if (i < KBINS)       g_pc[i]  = 0.0;
    if (i < CBINS)       g_pl[i]  = 0.0;
}

__device__ __forceinline__ float sigf(float t) {
    // 1/(1+e^-t): MUFU.EX2 + MUFU.RCP. Saturates correctly for |t| large.
    return __fdividef(1.0f, 1.0f + __expf(-t));
}

__device__ __forceinline__ float warp_sum(float v) {
    v += __shfl_xor_sync(0xffffffffu, v, 16);
    v += __shfl_xor_sync(0xffffffffu, v, 8);
    v += __shfl_xor_sync(0xffffffffu, v, 4);
    v += __shfl_xor_sync(0xffffffffu, v, 2);
    v += __shfl_xor_sync(0xffffffffu, v, 1);
    return v;
}

__global__ void __launch_bounds__(BLOCK)
nid_main(const float* __restrict__ cam, const float* __restrict__ lab) {
    // Per-thread Pc scratch: scr[k*BLOCK + tid] -> lanes hit distinct banks
    __shared__ float scr[KBINS*BLOCK];
    const int tid  = threadIdx.x;
    const int lane = tid & 31;

    float aPcl[KBINS*CBINS];
    float aPc[KBINS];
    float aPl[CBINS];
    #pragma unroll
    for (int i = 0; i < KBINS*CBINS; i++) aPcl[i] = 0.f;
    #pragma unroll
    for (int i = 0; i < KBINS; i++) aPc[i] = 0.f;
    #pragma unroll
    for (int i = 0; i < CBINS; i++) aPl[i] = 0.f;

    const float EXP_NEG_125 = 3.7266532e-06f;   // e^-12.5

    const int stride = GRID*BLOCK;
    for (int n = blockIdx.x*BLOCK + tid; n < NPOS; n += stride) {
        #pragma unroll
        for (int k = 0; k < KBINS; k++) scr[k*BLOCK + tid] = 0.f;

        float Pl0 = 0.f, Pl1 = 0.f, Pl2 = 0.f, Pl3 = 0.f;

        #pragma unroll
        for (int b = 0; b < BATCH; b++) {
            // ---- camera gray + 2-edge soft binning (telescoped sigmoids) ----
            const float* cb = cam + (size_t)b*3*NPOS + n;
            float x = (cb[0] + cb[NPOS] + cb[2*NPOS]) * (1.0f/3.0f);
            float s = x * 16.0f;                   // exact (pow2 scale)
            int k0 = (int)floorf(s);
            k0 = min(KBINS-1, max(0, k0));
            float f = s - (float)k0;               // frac position in bin
            // Edge sigmoids sharing one exp:
            //   Elo = sig(12.5 f)      = u/(1+u),      u = e^{12.5 f}
            //   Ehi = sig(12.5 (f-1))  = v/(1+v),      v = u * e^{-12.5}
            float u = __expf(12.5f * f);
            float v = u * EXP_NEG_125;
            float Elo = 1.0f - __fdividef(1.0f, 1.0f + u);
            float Ehi = 1.0f - __fdividef(1.0f, 1.0f + v);
            scr[k0*BLOCK + tid] += Elo - Ehi;
            if (k0 > 0)        scr[(k0-1)*BLOCK + tid] += 1.0f - Elo;
            if (k0 < KBINS-1)  scr[(k0+1)*BLOCK + tid] += Ehi;

            // ---- label soft-argmax ----
            const float* lb = lab + (size_t)b*4*NPOS + n;
            float a0 = lb[0], a1 = lb[NPOS], a2 = lb[2*NPOS], a3 = lb[3*NPOS];
            float amax = fmaxf(fmaxf(a0, a1), fmaxf(a2, a3));
            float e0 = __expf((a0 - amax) * 500.0f);
            float e1 = __expf((a1 - amax) * 500.0f);
            float e2 = __expf((a2 - amax) * 500.0f);
            float e3 = __expf((a3 - amax) * 500.0f);
            float den = e0 + e1 + e2 + e3 + 1e-12f;
            float num = e1 + 2.0f*e2 + 3.0f*e3;
            float y = __fdividef(num, den);

            // ---- label binning: usually exactly one-hot (bw=0.001) ----
            float ry = rintf(y);
            float r  = y - ry;
            if (fabsf(r) < 0.48f) {
                int m = (int)ry;
                Pl0 += (m == 0) ? 1.0f : 0.0f;
                Pl1 += (m == 1) ? 1.0f : 0.0f;
                Pl2 += (m == 2) ? 1.0f : 0.0f;
                Pl3 += (m == 3) ? 1.0f : 0.0f;
            } else {
                // rare near-half-integer case: exact sigmoids
                Pl0 += sigf((y + 0.5f)*1000.0f) - sigf((y - 0.5f)*1000.0f);
                Pl1 += sigf((y - 0.5f)*1000.0f) - sigf((y - 1.5f)*1000.0f);
                Pl2 += sigf((y - 1.5f)*1000.0f) - sigf((y - 2.5f)*1000.0f);
                Pl3 += sigf((y - 2.5f)*1000.0f) - sigf((y - 3.5f)*1000.0f);
            }
        }

        // ---- dense outer-product accumulate into registers ----
        #pragma unroll
        for (int k = 0; k < KBINS; k++) {
            float v = scr[k*BLOCK + tid];
            aPc[k] += v;
            aPcl[4*k + 0] += v * Pl0;
            aPcl[4*k + 1] += v * Pl1;
            aPcl[4*k + 2] += v * Pl2;
            aPcl[4*k + 3] += v * Pl3;
        }
        aPl[0] += Pl0; aPl[1] += Pl1; aPl[2] += Pl2; aPl[3] += Pl3;
    }

    // ---- reduce: warp shuffle + fp64 global atomics ----
    #pragma unroll
    for (int i = 0; i < KBINS*CBINS; i++) {
        float v = warp_sum(aPcl[i]);
        if (lane == 0) atomicAdd(&g_pcl[i], (double)v);
    }
    #pragma unroll
    for (int i = 0; i < KBINS; i++) {
        float v = warp_sum(aPc[i]);
        if (lane == 0) atomicAdd(&g_pc[i], (double)v);
    }
    #pragma unroll
    for (int i = 0; i < CBINS; i++) {
        float v = warp_sum(aPl[i]);
        if (lane == 0) atomicAdd(&g_pl[i], (double)v);
    }
}

__global__ void finalize_k(float* __restrict__ out) {
    if (threadIdx.x != 0 || blockIdx.x != 0) return;
    double spcl = 0.0, spc = 0.0, spl = 0.0;
    for (int i = 0; i < KBINS*CBINS; i++) spcl += g_pcl[i];
    for (int i = 0; i < KBINS; i++)       spc  += g_pc[i];
    for (int i = 0; i < CBINS; i++)       spl  += g_pl[i];
    double I = 0.0, H = 0.0;
    for (int k = 0; k < KBINS; k++) {
        double pc = g_pc[k] / spc;
        for (int c = 0; c < CBINS; c++) {
            double p  = g_pcl[4*k + c] / spcl;
            double o  = pc * (g_pl[c] / spl);
            double lp = log(p + 1e-7);
            double lo = log(o + 1e-7);
            I += p * (lp - lo);
            H -= p * lp;
        }
    }
    double nid = 1.0 - I / H;
    out[0] = (float)((nid - 0.95) * 20.0);
}

extern "C" void kernel_launch(void* const* d_in, const int* in_sizes, int n_in,
                              void* d_out, int out_size) {
    const float* cam = (const float*)d_in[0];
    const float* lab = (const float*)d_in[1];
    float* out = (float*)d_out;
    zero_acc<<<1, 64>>>();
    nid_main<<<GRID, BLOCK>>>(cam, lab);
    finalize_k<<<1, 1>>>(out);
}

// round 16
// speedup vs baseline: 1.1759x; 1.1759x over previous
#include <cuda_runtime.h>
#include <math.h>

#define NPOS   (512*1024)
#define BATCH  8
#define KBINS  16
#define CBINS  4
#define NACC   (KBINS*CBINS + KBINS + CBINS)   // 84
#define BLOCK  128
#define GRIDN  1024
#define ITERS  (NPOS / (GRIDN*BLOCK))          // 4

// Per-block partials: fully overwritten every launch (no zeroing needed).
__device__ float g_part[GRIDN * NACC];
// Self-resetting arrival counter: atomicInc wraps to 0 after GRIDN arrivals.
__device__ unsigned int g_ctr = 0;

__device__ __forceinline__ float sigf(float t) {
    return __fdividef(1.0f, 1.0f + __expf(-t));
}

__device__ __forceinline__ float warp_sum(float v) {
    v += __shfl_xor_sync(0xffffffffu, v, 16);
    v += __shfl_xor_sync(0xffffffffu, v, 8);
    v += __shfl_xor_sync(0xffffffffu, v, 4);
    v += __shfl_xor_sync(0xffffffffu, v, 2);
    v += __shfl_xor_sync(0xffffffffu, v, 1);
    return v;
}

__global__ void __launch_bounds__(BLOCK)
nid_fused(const float* __restrict__ cam, const float* __restrict__ lab,
          float* __restrict__ out) {
    __shared__ float scr[KBINS*BLOCK];      // per-thread Pc scratch (bank-clean)
    __shared__ float red[NACC*4];           // cross-warp partials
    __shared__ double dred[NACC];
    __shared__ int s_last;

    const int tid  = threadIdx.x;
    const int lane = tid & 31;
    const int wid  = tid >> 5;

    float aPcl[KBINS*CBINS], aPc[KBINS], aPl[CBINS];
    #pragma unroll
    for (int i = 0; i < KBINS*CBINS; i++) aPcl[i] = 0.f;
    #pragma unroll
    for (int i = 0; i < KBINS; i++) aPc[i] = 0.f;
    #pragma unroll
    for (int i = 0; i < CBINS; i++) aPl[i] = 0.f;

    const float EXP_NEG_125 = 3.7266532e-06f;   // e^-12.5
    const int stride = GRIDN*BLOCK;
    int n = blockIdx.x*BLOCK + tid;

    #pragma unroll 1
    for (int it = 0; it < ITERS; it++, n += stride) {
        // ---- front-batch ALL 56 loads for this position (max MLP) ----
        float cv[BATCH*3], lv[BATCH*4];
        #pragma unroll
        for (int j = 0; j < BATCH*3; j++) cv[j] = cam[(size_t)j*NPOS + n];
        #pragma unroll
        for (int j = 0; j < BATCH*4; j++) lv[j] = lab[(size_t)j*NPOS + n];

        #pragma unroll
        for (int k = 0; k < KBINS; k++) scr[k*BLOCK + tid] = 0.f;

        float Pl0 = 0.f, Pl1 = 0.f, Pl2 = 0.f, Pl3 = 0.f;

        #pragma unroll
        for (int b = 0; b < BATCH; b++) {
            // ---- camera: gray -> 2 edge sigmoids -> 3-bin branch-free scatter ----
            float x = (cv[3*b] + cv[3*b+1] + cv[3*b+2]) * (1.0f/3.0f);
            float s = x * 16.0f;
            int k0 = (int)floorf(s);
            k0 = min(KBINS-1, max(0, k0));
            float f = s - (float)k0;
            float u = __expf(12.5f * f);
            float Elo = __fdividef(u, 1.0f + u);
            float v  = u * EXP_NEG_125;
            float Ehi = __fdividef(v, 1.0f + v);
            // clamped targets + zeroed values: no divergence
            int klo = max(k0-1, 0), khi = min(k0+1, KBINS-1);
            float wlo = (k0 > 0)       ? (1.0f - Elo) : 0.0f;
            float whi = (k0 < KBINS-1) ? Ehi          : 0.0f;
            scr[k0*BLOCK + tid] += Elo - Ehi;
            scr[klo*BLOCK + tid] += wlo;
            scr[khi*BLOCK + tid] += whi;

            // ---- label: softmax-argmax -> (almost always) exact one-hot ----
            float a0 = lv[4*b], a1 = lv[4*b+1], a2 = lv[4*b+2], a3 = lv[4*b+3];
            float amax = fmaxf(fmaxf(a0, a1), fmaxf(a2, a3));
            float e0 = __expf((a0 - amax) * 500.0f);
            float e1 = __expf((a1 - amax) * 500.0f);
            float e2 = __expf((a2 - amax) * 500.0f);
            float e3 = __expf((a3 - amax) * 500.0f);
            float den = e0 + e1 + e2 + e3 + 1e-12f;
            float y = __fdividef(e1 + 2.0f*e2 + 3.0f*e3, den);

            float ry = rintf(y);
            float d  = y - ry;
            int   m  = (int)ry;
            if (__ballot_sync(0xffffffffu, fabsf(d) >= 0.47f)) {
                // rare: exact 3-neighbor sigmoid weights (exact in fp32 for all lanes)
                float w  = sigf((d + 0.5f) * 1000.0f);
                float v2 = sigf((d - 0.5f) * 1000.0f);
                float cm = w - v2;
                Pl0 += (m==0) ? cm : (m==1) ? (1.0f-w) : (m==-1) ? v2 : 0.0f;
                Pl1 += (m==1) ? cm : (m==2) ? (1.0f-w) : (m==0)  ? v2 : 0.0f;
                Pl2 += (m==2) ? cm : (m==3) ? (1.0f-w) : (m==1)  ? v2 : 0.0f;
                Pl3 += (m==3) ? cm : (m==4) ? (1.0f-w) : (m==2)  ? v2 : 0.0f;
            } else {
                Pl0 += (m == 0) ? 1.0f : 0.0f;
                Pl1 += (m == 1) ? 1.0f : 0.0f;
                Pl2 += (m == 2) ? 1.0f : 0.0f;
                Pl3 += (m == 3) ? 1.0f : 0.0f;
            }
        }

        // ---- dense outer-product into register accumulators ----
        #pragma unroll
        for (int k = 0; k < KBINS; k++) {
            float v = scr[k*BLOCK + tid];
            aPc[k] += v;
            aPcl[4*k + 0] += v * Pl0;
            aPcl[4*k + 1] += v * Pl1;
            aPcl[4*k + 2] += v * Pl2;
            aPcl[4*k + 3] += v * Pl3;
        }
        aPl[0] += Pl0; aPl[1] += Pl1; aPl[2] += Pl2; aPl[3] += Pl3;
    }

    // ---- block reduction: shuffle within warp, smem across 4 warps ----
    #pragma unroll
    for (int i = 0; i < KBINS*CBINS; i++) {
        float v = warp_sum(aPcl[i]);
        if (lane == 0) red[i*4 + wid] = v;
    }
    #pragma unroll
    for (int i = 0; i < KBINS; i++) {
        float v = warp_sum(aPc[i]);
        if (lane == 0) red[(KBINS*CBINS + i)*4 + wid] = v;
    }
    #pragma unroll
    for (int i = 0; i < CBINS; i++) {
        float v = warp_sum(aPl[i]);
        if (lane == 0) red[(KBINS*CBINS + KBINS + i)*4 + wid] = v;
    }
    __syncthreads();

    if (tid < NACC) {
        float s = red[tid*4] + red[tid*4+1] + red[tid*4+2] + red[tid*4+3];
        g_part[(size_t)blockIdx.x*NACC + tid] = s;
    }
    __threadfence();
    __syncthreads();
    if (tid == 0) {
        unsigned int old = atomicInc(&g_ctr, GRIDN - 1);   // wraps to 0: graph-safe
        s_last = (old == GRIDN - 1);
    }
    __syncthreads();

    if (s_last) {
        if (tid < NACC) {
            double acc = 0.0;
            for (int j = 0; j < GRIDN; j++)
                acc += (double)g_part[(size_t)j*NACC + tid];
            dred[tid] = acc;
        }
        __syncthreads();
        if (tid == 0) {
            double spcl = 0.0, spc = 0.0, spl = 0.0;
            for (int i = 0; i < KBINS*CBINS; i++) spcl += dred[i];
            for (int i = 0; i < KBINS; i++)       spc  += dred[KBINS*CBINS + i];
            for (int i = 0; i < CBINS; i++)       spl  += dred[KBINS*CBINS + KBINS + i];
            double I = 0.0, H = 0.0;
            for (int k = 0; k < KBINS; k++) {
                double pc = dred[KBINS*CBINS + k] / spc;
                for (int c = 0; c < CBINS; c++) {
                    double p  = dred[4*k + c] / spcl;
                    double o  = pc * (dred[KBINS*CBINS + KBINS + c] / spl);
                    double lp = log(p + 1e-7);
                    double lo = log(o + 1e-7);
                    I += p * (lp - lo);
                    H -= p * lp;
                }
            }
            double nid = 1.0 - I / H;
            out[0] = (float)((nid - 0.95) * 20.0);
        }
    }
}

extern "C" void kernel_launch(void* const* d_in, const int* in_sizes, int n_in,
                              void* d_out, int out_size) {
    const float* cam = (const float*)d_in[0];
    const float* lab = (const float*)d_in[1];
    float* out = (float*)d_out;
    nid_fused<<<GRIDN, BLOCK>>>(cam, lab, out);
}